// round 2
// baseline (speedup 1.0000x reference)
#include <cuda_runtime.h>
#include <cstddef>

// Problem constants
#define SDIM   512            // sequence length S
#define DDIM   512            // model dim D
#define BDIM   16             // batch
#define HDIM   8              // heads
#define LNUM   6              // layers
#define FDIM   2048           // ff dim
#define MSROWS (BDIM * SDIM)  // 8192 rows in (B*S, D) matrices
#define DK     64             // head dim

// ---------------- scratch (static device globals; no allocations) ----------------
__device__ float g_h  [MSROWS * DDIM];
__device__ float g_q  [MSROWS * DDIM];
__device__ float g_k  [MSROWS * DDIM];
__device__ float g_v  [MSROWS * DDIM];
__device__ float g_h1 [MSROWS * DDIM];
__device__ float g_tmp[MSROWS * DDIM];
__device__ float g_ff [MSROWS * FDIM];
__device__ float g_sc [(size_t)BDIM * HDIM * SDIM * SDIM];  // 33.5M floats = 128MB
__device__ float g_pb [SDIM * DDIM];

// ---------------- relative position bias ----------------
// pos_bias[s,d] = (1/S) * sum_q rel_emb[clip(q-s,-32,32)+32, d]
__global__ void posbias_kernel(const float* __restrict__ rel_emb, float* __restrict__ pb) {
    int s = blockIdx.x;
    int d = threadIdx.x;  // 512 threads
    float acc = 0.f;
    // bin 0: rel = -32  <=>  q <= s-32  -> count = max(0, s-31)
    int c0 = s - 31; if (c0 < 0) c0 = 0;
    acc += (float)c0 * rel_emb[0 * DDIM + d];
    // bin 64: rel = +32 <=> q >= s+32 -> count = max(0, 480-s)
    int c64 = 480 - s; if (c64 < 0) c64 = 0;
    acc += (float)c64 * rel_emb[64 * DDIM + d];
    // middle bins r=1..63 : rel = r-32 in [-31,31], count 1 iff 0 <= s+rel < S
    #pragma unroll 1
    for (int r = 1; r < 64; r++) {
        int qq = s + r - 32;
        if (qq >= 0 && qq < SDIM) acc += rel_emb[r * DDIM + d];
    }
    pb[s * DDIM + d] = acc * (1.0f / (float)SDIM);
}

// ---------------- generic 64x64 tiled GEMM, 4x4 register blocking ----------------
// C[m,n] = act( sum_k A[m,k]*B[k,n] + bias[n] + resid )
// RMODE: 0 = no residual, 1 = resid[m,n] (same shape), 2 = resid[(m % 512), n] (pos bias)
template<bool RELU, int RMODE>
__global__ void gemm64(const float* __restrict__ A, const float* __restrict__ B,
                       const float* __restrict__ bias, const float* __restrict__ resid,
                       float* __restrict__ C, int M, int N, int K)
{
    __shared__ float As[16][65];   // transposed, padded
    __shared__ float Bs[16][64];

    int tid = threadIdx.x;           // 256
    int tx = tid & 15, ty = tid >> 4;
    int tx4 = tx * 4, ty4 = ty * 4;
    int ar = tid >> 2, ac = (tid & 3) * 4;   // A tile: 64 rows x 16 cols, 4 consecutive k each
    int br = tid >> 4, bc = (tid & 15) * 4;  // B tile: 16 rows x 64 cols, 4 consecutive n each

    const float* Ab = A + (size_t)blockIdx.y * 64 * K;
    const float* Bb = B + blockIdx.x * 64;

    float acc[4][4] = {};

    for (int k0 = 0; k0 < K; k0 += 16) {
        float4 av = *(const float4*)(Ab + (size_t)ar * K + k0 + ac);
        As[ac + 0][ar] = av.x; As[ac + 1][ar] = av.y;
        As[ac + 2][ar] = av.z; As[ac + 3][ar] = av.w;
        float4 bv = *(const float4*)(Bb + (size_t)(k0 + br) * N + bc);
        *(float4*)&Bs[br][bc] = bv;
        __syncthreads();
        #pragma unroll
        for (int kk = 0; kk < 16; kk++) {
            float a0 = As[kk][ty4 + 0], a1 = As[kk][ty4 + 1];
            float a2 = As[kk][ty4 + 2], a3 = As[kk][ty4 + 3];
            float4 b4 = *(const float4*)&Bs[kk][tx4];
            acc[0][0] += a0 * b4.x; acc[0][1] += a0 * b4.y; acc[0][2] += a0 * b4.z; acc[0][3] += a0 * b4.w;
            acc[1][0] += a1 * b4.x; acc[1][1] += a1 * b4.y; acc[1][2] += a1 * b4.z; acc[1][3] += a1 * b4.w;
            acc[2][0] += a2 * b4.x; acc[2][1] += a2 * b4.y; acc[2][2] += a2 * b4.z; acc[2][3] += a2 * b4.w;
            acc[3][0] += a3 * b4.x; acc[3][1] += a3 * b4.y; acc[3][2] += a3 * b4.z; acc[3][3] += a3 * b4.w;
        }
        __syncthreads();
    }

    int row0 = blockIdx.y * 64 + ty4;
    int col0 = blockIdx.x * 64 + tx4;
    float4 bb = *(const float4*)(bias + col0);
    #pragma unroll
    for (int i = 0; i < 4; i++) {
        float4 r;
        r.x = acc[i][0] + bb.x; r.y = acc[i][1] + bb.y;
        r.z = acc[i][2] + bb.z; r.w = acc[i][3] + bb.w;
        if (RMODE == 1) {
            float4 rv = *(const float4*)(resid + (size_t)(row0 + i) * N + col0);
            r.x += rv.x; r.y += rv.y; r.z += rv.z; r.w += rv.w;
        } else if (RMODE == 2) {
            float4 rv = *(const float4*)(resid + (size_t)((row0 + i) & (SDIM - 1)) * N + col0);
            r.x += rv.x; r.y += rv.y; r.z += rv.z; r.w += rv.w;
        }
        if (RELU) {
            r.x = fmaxf(r.x, 0.f); r.y = fmaxf(r.y, 0.f);
            r.z = fmaxf(r.z, 0.f); r.w = fmaxf(r.w, 0.f);
        }
        *(float4*)(C + (size_t)(row0 + i) * N + col0) = r;
    }
}

// ---------------- batched attention score: S = Q K^T * 0.125 ----------------
// grid: (S/64, S/64, B*H); Q,K in (B,S,D) layout, head slice h*64
__global__ void attn_scores(const float* __restrict__ Q, const float* __restrict__ Kt,
                            float* __restrict__ Sc)
{
    int z = blockIdx.z;           // b*H + h
    int b = z >> 3, h = z & 7;
    size_t base = ((size_t)b * SDIM) * DDIM + (size_t)h * DK;
    const float* Arow = Q  + base + (size_t)blockIdx.y * 64 * DDIM;
    const float* Bcol = Kt + base + (size_t)blockIdx.x * 64 * DDIM;
    float* C = Sc + (size_t)z * SDIM * SDIM + (size_t)blockIdx.y * 64 * SDIM + blockIdx.x * 64;

    __shared__ float As[16][65];
    __shared__ float Bs[16][65];
    int tid = threadIdx.x;
    int tx = tid & 15, ty = tid >> 4;
    int tx4 = tx * 4, ty4 = ty * 4;
    int ar = tid >> 2, ac = (tid & 3) * 4;

    float acc[4][4] = {};
    for (int k0 = 0; k0 < DK; k0 += 16) {
        float4 av = *(const float4*)(Arow + (size_t)ar * DDIM + k0 + ac);
        As[ac + 0][ar] = av.x; As[ac + 1][ar] = av.y;
        As[ac + 2][ar] = av.z; As[ac + 3][ar] = av.w;
        float4 bv = *(const float4*)(Bcol + (size_t)ar * DDIM + k0 + ac);
        Bs[ac + 0][ar] = bv.x; Bs[ac + 1][ar] = bv.y;
        Bs[ac + 2][ar] = bv.z; Bs[ac + 3][ar] = bv.w;
        __syncthreads();
        #pragma unroll
        for (int kk = 0; kk < 16; kk++) {
            float a0 = As[kk][ty4 + 0], a1 = As[kk][ty4 + 1];
            float a2 = As[kk][ty4 + 2], a3 = As[kk][ty4 + 3];
            float b0 = Bs[kk][tx4 + 0], b1 = Bs[kk][tx4 + 1];
            float b2 = Bs[kk][tx4 + 2], b3 = Bs[kk][tx4 + 3];
            acc[0][0] += a0 * b0; acc[0][1] += a0 * b1; acc[0][2] += a0 * b2; acc[0][3] += a0 * b3;
            acc[1][0] += a1 * b0; acc[1][1] += a1 * b1; acc[1][2] += a1 * b2; acc[1][3] += a1 * b3;
            acc[2][0] += a2 * b0; acc[2][1] += a2 * b1; acc[2][2] += a2 * b2; acc[2][3] += a2 * b3;
            acc[3][0] += a3 * b0; acc[3][1] += a3 * b1; acc[3][2] += a3 * b2; acc[3][3] += a3 * b3;
        }
        __syncthreads();
    }
    #pragma unroll
    for (int i = 0; i < 4; i++) {
        float4 r;
        r.x = acc[i][0] * 0.125f; r.y = acc[i][1] * 0.125f;
        r.z = acc[i][2] * 0.125f; r.w = acc[i][3] * 0.125f;
        *(float4*)(C + (size_t)(ty4 + i) * SDIM + tx4) = r;
    }
}

// ---------------- batched ctx = attn @ V ----------------
// grid: (1, S/64, B*H); output to (B,S,D) layout head slice
__global__ void attn_ctx(const float* __restrict__ P, const float* __restrict__ V,
                         float* __restrict__ O)
{
    int z = blockIdx.z;
    int b = z >> 3, h = z & 7;
    const float* A  = P + (size_t)z * SDIM * SDIM + (size_t)blockIdx.y * 64 * SDIM;
    const float* Bp = V + ((size_t)b * SDIM) * DDIM + (size_t)h * DK;
    float* C = O + ((size_t)b * SDIM + (size_t)blockIdx.y * 64) * DDIM + h * DK;

    __shared__ float As[16][65];
    __shared__ float Bs[16][64];
    int tid = threadIdx.x;
    int tx = tid & 15, ty = tid >> 4;
    int tx4 = tx * 4, ty4 = ty * 4;
    int ar = tid >> 2, ac = (tid & 3) * 4;
    int br = tid >> 4, bc = (tid & 15) * 4;

    float acc[4][4] = {};
    for (int k0 = 0; k0 < SDIM; k0 += 16) {
        float4 av = *(const float4*)(A + (size_t)ar * SDIM + k0 + ac);
        As[ac + 0][ar] = av.x; As[ac + 1][ar] = av.y;
        As[ac + 2][ar] = av.z; As[ac + 3][ar] = av.w;
        float4 bv = *(const float4*)(Bp + (size_t)(k0 + br) * DDIM + bc);
        *(float4*)&Bs[br][bc] = bv;
        __syncthreads();
        #pragma unroll
        for (int kk = 0; kk < 16; kk++) {
            float a0 = As[kk][ty4 + 0], a1 = As[kk][ty4 + 1];
            float a2 = As[kk][ty4 + 2], a3 = As[kk][ty4 + 3];
            float4 b4 = *(const float4*)&Bs[kk][tx4];
            acc[0][0] += a0 * b4.x; acc[0][1] += a0 * b4.y; acc[0][2] += a0 * b4.z; acc[0][3] += a0 * b4.w;
            acc[1][0] += a1 * b4.x; acc[1][1] += a1 * b4.y; acc[1][2] += a1 * b4.z; acc[1][3] += a1 * b4.w;
            acc[2][0] += a2 * b4.x; acc[2][1] += a2 * b4.y; acc[2][2] += a2 * b4.z; acc[2][3] += a2 * b4.w;
            acc[3][0] += a3 * b4.x; acc[3][1] += a3 * b4.y; acc[3][2] += a3 * b4.z; acc[3][3] += a3 * b4.w;
        }
        __syncthreads();
    }
    #pragma unroll
    for (int i = 0; i < 4; i++) {
        float4 r;
        r.x = acc[i][0]; r.y = acc[i][1]; r.z = acc[i][2]; r.w = acc[i][3];
        *(float4*)(C + (size_t)(ty4 + i) * DDIM + tx4) = r;
    }
}

// ---------------- block reduce helpers (128 threads) ----------------
__device__ __forceinline__ float blockReduceSum128(float v, float* shm) {
    #pragma unroll
    for (int o = 16; o > 0; o >>= 1) v += __shfl_xor_sync(0xffffffffu, v, o);
    if ((threadIdx.x & 31) == 0) shm[threadIdx.x >> 5] = v;
    __syncthreads();
    v = shm[0] + shm[1] + shm[2] + shm[3];
    __syncthreads();
    return v;
}
__device__ __forceinline__ float blockReduceMax128(float v, float* shm) {
    #pragma unroll
    for (int o = 16; o > 0; o >>= 1) v = fmaxf(v, __shfl_xor_sync(0xffffffffu, v, o));
    if ((threadIdx.x & 31) == 0) shm[threadIdx.x >> 5] = v;
    __syncthreads();
    v = fmaxf(fmaxf(shm[0], shm[1]), fmaxf(shm[2], shm[3]));
    __syncthreads();
    return v;
}

// ---------------- softmax over 512-length rows, in place ----------------
__global__ void softmax512(float* __restrict__ data) {
    __shared__ float shm[4];
    size_t row = blockIdx.x;
    float* p = data + row * SDIM;
    int t = threadIdx.x;  // 128
    float4 v = ((float4*)p)[t];
    float m = fmaxf(fmaxf(v.x, v.y), fmaxf(v.z, v.w));
    m = blockReduceMax128(m, shm);
    v.x = __expf(v.x - m); v.y = __expf(v.y - m);
    v.z = __expf(v.z - m); v.w = __expf(v.w - m);
    float s = v.x + v.y + v.z + v.w;
    s = blockReduceSum128(s, shm);
    float inv = 1.0f / s;
    v.x *= inv; v.y *= inv; v.z *= inv; v.w *= inv;
    ((float4*)p)[t] = v;
}

// ---------------- layernorm over 512-length rows ----------------
__global__ void layernorm512(const float* __restrict__ in, const float* __restrict__ g,
                             const float* __restrict__ bta, float* __restrict__ out)
{
    __shared__ float shm[4];
    size_t row = blockIdx.x;
    const float* p = in + row * DDIM;
    int t = threadIdx.x;  // 128
    float4 v = ((const float4*)p)[t];
    float s = v.x + v.y + v.z + v.w;
    s = blockReduceSum128(s, shm);
    float mu = s * (1.0f / (float)DDIM);
    float dx = v.x - mu, dy = v.y - mu, dz = v.z - mu, dw = v.w - mu;
    float sq = dx * dx + dy * dy + dz * dz + dw * dw;
    sq = blockReduceSum128(sq, shm);
    float var = sq * (1.0f / (float)DDIM);
    float inv = rsqrtf(var + 1e-5f);
    float4 gg = ((const float4*)g)[t];
    float4 bb = ((const float4*)bta)[t];
    float4 o;
    o.x = dx * inv * gg.x + bb.x;
    o.y = dy * inv * gg.y + bb.y;
    o.z = dz * inv * gg.z + bb.z;
    o.w = dw * inv * gg.w + bb.w;
    ((float4*)(out + row * DDIM))[t] = o;
}

// ---------------- final projection: out = h @ out_W + out_b (N=1) ----------------
__global__ void outproj(const float* __restrict__ h, const float* __restrict__ W,
                        const float* __restrict__ ob, float* __restrict__ out)
{
    __shared__ float shm[4];
    size_t row = blockIdx.x;
    int t = threadIdx.x;  // 128
    float4 v = ((const float4*)(h + row * DDIM))[t];
    float4 w = ((const float4*)W)[t];
    float s = v.x * w.x + v.y * w.y + v.z * w.z + v.w * w.w;
    s = blockReduceSum128(s, shm);
    if (t == 0) out[row] = s + ob[0];
}

// ---------------- host side ----------------
extern "C" void kernel_launch(void* const* d_in, const int* in_sizes, int n_in,
                              void* d_out, int out_size)
{
    (void)in_sizes; (void)n_in; (void)out_size;
    const float* x       = (const float*)d_in[0];
    const float* in_W    = (const float*)d_in[1];
    const float* in_b    = (const float*)d_in[2];
    const float* rel_emb = (const float*)d_in[3];
    const float* qkvo_W  = (const float*)d_in[4];
    const float* qkvo_b  = (const float*)d_in[5];
    const float* ln_g    = (const float*)d_in[6];
    const float* ln_b    = (const float*)d_in[7];
    const float* ff_W1   = (const float*)d_in[8];
    const float* ff_b1   = (const float*)d_in[9];
    const float* ff_W2   = (const float*)d_in[10];
    const float* ff_b2   = (const float*)d_in[11];
    const float* out_W   = (const float*)d_in[12];
    const float* out_b   = (const float*)d_in[13];

    float *h, *q, *k, *v, *h1, *tmp, *ff, *sc, *pb;
    cudaGetSymbolAddress((void**)&h,   g_h);
    cudaGetSymbolAddress((void**)&q,   g_q);
    cudaGetSymbolAddress((void**)&k,   g_k);
    cudaGetSymbolAddress((void**)&v,   g_v);
    cudaGetSymbolAddress((void**)&h1,  g_h1);
    cudaGetSymbolAddress((void**)&tmp, g_tmp);
    cudaGetSymbolAddress((void**)&ff,  g_ff);
    cudaGetSymbolAddress((void**)&sc,  g_sc);
    cudaGetSymbolAddress((void**)&pb,  g_pb);

    // 1) relative position bias (S x D)
    posbias_kernel<<<SDIM, DDIM>>>(rel_emb, pb);

    // 2) input projection + pos bias: h = x @ in_W + in_b + pb[s]
    gemm64<false, 2><<<dim3(DDIM / 64, MSROWS / 64), 256>>>(
        x, in_W, in_b, pb, h, MSROWS, DDIM, 64);

    // 3) layers
    for (int l = 0; l < LNUM; l++) {
        const float* Wq = qkvo_W + ((size_t)l * 4 + 0) * DDIM * DDIM;
        const float* Wk = qkvo_W + ((size_t)l * 4 + 1) * DDIM * DDIM;
        const float* Wv = qkvo_W + ((size_t)l * 4 + 2) * DDIM * DDIM;
        const float* Wo = qkvo_W + ((size_t)l * 4 + 3) * DDIM * DDIM;
        const float* bq = qkvo_b + ((size_t)l * 4 + 0) * DDIM;
        const float* bk = qkvo_b + ((size_t)l * 4 + 1) * DDIM;
        const float* bv = qkvo_b + ((size_t)l * 4 + 2) * DDIM;
        const float* bo = qkvo_b + ((size_t)l * 4 + 3) * DDIM;
        const float* g0 = ln_g + ((size_t)l * 2 + 0) * DDIM;
        const float* b0 = ln_b + ((size_t)l * 2 + 0) * DDIM;
        const float* g1 = ln_g + ((size_t)l * 2 + 1) * DDIM;
        const float* b1l = ln_b + ((size_t)l * 2 + 1) * DDIM;
        const float* W1 = ff_W1 + (size_t)l * DDIM * FDIM;
        const float* fb1 = ff_b1 + (size_t)l * FDIM;
        const float* W2 = ff_W2 + (size_t)l * FDIM * DDIM;
        const float* fb2 = ff_b2 + (size_t)l * DDIM;

        dim3 gproj(DDIM / 64, MSROWS / 64);
        gemm64<false, 0><<<gproj, 256>>>(h, Wq, bq, nullptr, q, MSROWS, DDIM, DDIM);
        gemm64<false, 0><<<gproj, 256>>>(h, Wk, bk, nullptr, k, MSROWS, DDIM, DDIM);
        gemm64<false, 0><<<gproj, 256>>>(h, Wv, bv, nullptr, v, MSROWS, DDIM, DDIM);

        attn_scores<<<dim3(SDIM / 64, SDIM / 64, BDIM * HDIM), 256>>>(q, k, sc);
        softmax512<<<BDIM * HDIM * SDIM, 128>>>(sc);
        attn_ctx<<<dim3(1, SDIM / 64, BDIM * HDIM), 256>>>(sc, v, tmp);

        // attention output proj + residual(h) -> q (pre-LN1)
        gemm64<false, 1><<<gproj, 256>>>(tmp, Wo, bo, h, q, MSROWS, DDIM, DDIM);
        layernorm512<<<MSROWS, 128>>>(q, g0, b0, h1);

        // FF
        gemm64<true, 0><<<dim3(FDIM / 64, MSROWS / 64), 256>>>(
            h1, W1, fb1, nullptr, ff, MSROWS, FDIM, DDIM);
        gemm64<false, 1><<<gproj, 256>>>(ff, W2, fb2, h1, tmp, MSROWS, DDIM, FDIM);
        layernorm512<<<MSROWS, 128>>>(tmp, g1, b1l, h);
    }

    // 4) output projection
    outproj<<<MSROWS, 128>>>(h, out_W, out_b, (float*)d_out);
}

// round 5
// speedup vs baseline: 2.8130x; 2.8130x over previous
#include <cuda_runtime.h>
#include <cuda_bf16.h>
#include <cstdint>
#include <cstddef>

// ---------------- problem constants ----------------
#define SDIM   512
#define DDIM   512
#define BDIM   16
#define HDIM   8
#define LNUM   6
#define FDIM   2048
#define MSROWS (BDIM * SDIM)   // 8192
#define DK     64

// ---------------- low-level helpers (sm_80+ PTX only) ----------------
__device__ __forceinline__ uint32_t smem_u32(const void* p) {
    uint32_t a;
    asm("{ .reg .u64 t; cvta.to.shared.u64 t, %1; cvt.u32.u64 %0, t; }" : "=r"(a) : "l"(p));
    return a;
}
__device__ __forceinline__ void cp16(uint32_t dst, const void* src) {
    asm volatile("cp.async.cg.shared.global [%0], [%1], 16;" :: "r"(dst), "l"(src));
}
__device__ __forceinline__ void ldsm4(uint32_t a[4], uint32_t addr) {
    asm volatile("ldmatrix.sync.aligned.m8n8.x4.shared.b16 {%0,%1,%2,%3}, [%4];"
        : "=r"(a[0]), "=r"(a[1]), "=r"(a[2]), "=r"(a[3]) : "r"(addr));
}
__device__ __forceinline__ void ldsm2(uint32_t a[2], uint32_t addr) {
    asm volatile("ldmatrix.sync.aligned.m8n8.x2.shared.b16 {%0,%1}, [%2];"
        : "=r"(a[0]), "=r"(a[1]) : "r"(addr));
}
__device__ __forceinline__ void ldsm2t(uint32_t a[2], uint32_t addr) {
    asm volatile("ldmatrix.sync.aligned.m8n8.x2.trans.shared.b16 {%0,%1}, [%2];"
        : "=r"(a[0]), "=r"(a[1]) : "r"(addr));
}
__device__ __forceinline__ void mma_bf16(float c[4], const uint32_t a[4], const uint32_t b[2]) {
    asm volatile(
        "mma.sync.aligned.m16n8k16.row.col.f32.bf16.bf16.f32 "
        "{%0,%1,%2,%3}, {%4,%5,%6,%7}, {%8,%9}, {%0,%1,%2,%3};"
        : "+f"(c[0]), "+f"(c[1]), "+f"(c[2]), "+f"(c[3])
        : "r"(a[0]), "r"(a[1]), "r"(a[2]), "r"(a[3]), "r"(b[0]), "r"(b[1]));
}
// swizzled offset in a tile with 128-byte rows (3-bit swizzle, conflict-free ldmatrix)
__device__ __forceinline__ uint32_t sw128(uint32_t row, uint32_t byte_in_row) {
    return row * 128u + (byte_in_row ^ ((row & 7u) << 4));
}
__device__ __forceinline__ uint32_t pack_bf2(float a, float b) {
    return (uint32_t)__bfloat16_as_ushort(__float2bfloat16(a)) |
           ((uint32_t)__bfloat16_as_ushort(__float2bfloat16(b)) << 16);
}
__device__ __forceinline__ void split2(float a, float b, uint32_t& hi, uint32_t& lo) {
    __nv_bfloat16 ha = __float2bfloat16(a), hb = __float2bfloat16(b);
    float ra = a - __bfloat162float(ha), rb = b - __bfloat162float(hb);
    hi = (uint32_t)__bfloat16_as_ushort(ha) | ((uint32_t)__bfloat16_as_ushort(hb) << 16);
    lo = (uint32_t)__bfloat16_as_ushort(__float2bfloat16(ra)) |
         ((uint32_t)__bfloat16_as_ushort(__float2bfloat16(rb)) << 16);
}

// ---------------- scratch (static device globals; no allocations) ----------------
__device__ float g_h  [MSROWS * DDIM];
__device__ float g_h1 [MSROWS * DDIM];
__device__ float g_t  [MSROWS * DDIM];
__device__ float g_sc [(size_t)BDIM * HDIM * SDIM * SDIM];  // fp32 scores
__device__ float g_pb [SDIM * DDIM];

__device__ __nv_bfloat16 g_xh[MSROWS * 64];       // x split
__device__ __nv_bfloat16 g_xl[MSROWS * 64];
__device__ __nv_bfloat16 g_ah[MSROWS * DDIM];     // generic activation split (h / ctx / h1)
__device__ __nv_bfloat16 g_al[MSROWS * DDIM];
__device__ __nv_bfloat16 g_fh[MSROWS * FDIM];     // ff split
__device__ __nv_bfloat16 g_fl[MSROWS * FDIM];
__device__ __nv_bfloat16 g_qh[MSROWS * DDIM];
__device__ __nv_bfloat16 g_ql[MSROWS * DDIM];
__device__ __nv_bfloat16 g_kh[MSROWS * DDIM];
__device__ __nv_bfloat16 g_kl[MSROWS * DDIM];
__device__ __nv_bfloat16 g_vh[MSROWS * DDIM];
__device__ __nv_bfloat16 g_vl[MSROWS * DDIM];
__device__ __nv_bfloat16 g_ph[(size_t)BDIM * HDIM * SDIM * SDIM];  // softmax out
__device__ __nv_bfloat16 g_pl[(size_t)BDIM * HDIM * SDIM * SDIM];

// transposed weights (hi/lo)
#define WT_IN    0
#define WT_QKVO  (512 * 64)
#define WT_W1    (WT_QKVO + 24 * 512 * 512)
#define WT_W2    (WT_W1 + 6 * 2048 * 512)
#define WT_TOTAL (WT_W2 + 6 * 512 * 2048)
__device__ __nv_bfloat16 g_wh[WT_TOTAL];
__device__ __nv_bfloat16 g_wl[WT_TOTAL];

// ---------------- the MMA GEMM ----------------
// C = act( alpha * (A @ B^T) + bias + resid ), bf16 hi/lo 3-pass split, fp32 accum.
// A: M x K (k-contiguous, stride lda).  B (non-trans): N x K (stride ldb).
// B (BTRANS, ctx mode): V in [k][n] layout (stride ldb), loaded via ldmatrix.trans.
// MODE: 0 plain, 1 scores (A,B = per-head slices of Q,K; C = per-z score tile),
//       2 ctx (A = P per z; B = V head slice; C = per-head slice of (B,S,D))
template<int BM, int BN, int WGM, int WGN, int MODE, bool BTRANS,
         bool RELU, int RMODE, bool HASBIAS, bool WF32, bool WSPLIT>
__global__ void __launch_bounds__(256, 1)
mma_gemm(const __nv_bfloat16* __restrict__ Ah, const __nv_bfloat16* __restrict__ Al, int lda,
         const __nv_bfloat16* __restrict__ Bh, const __nv_bfloat16* __restrict__ Bl, int ldb,
         const float* __restrict__ bias, const float* __restrict__ resid,
         float* __restrict__ C, __nv_bfloat16* __restrict__ Ch, __nv_bfloat16* __restrict__ Cl,
         int ldc, int K, float alpha)
{
    constexpr int ABYTES = BM * 128;
    constexpr int BBYTES = BTRANS ? (64 * BN * 2) : (BN * 128);
    constexpr int STAGE  = 2 * ABYTES + 2 * BBYTES;
    extern __shared__ char smem[];

    const int tid  = threadIdx.x;
    const int wid  = tid >> 5;
    const int lane = tid & 31;
    const int wm   = wid / WGN;
    const int wn   = wid % WGN;

    size_t aoff = 0, boff = 0, coff = 0;
    if (MODE == 1) {
        int bz = blockIdx.z;
        aoff = boff = ((size_t)(bz >> 3)) * ((size_t)SDIM * DDIM) + (size_t)(bz & 7) * DK;
        coff = (size_t)bz * SDIM * SDIM;
    } else if (MODE == 2) {
        int bz = blockIdx.z;
        aoff = (size_t)bz * SDIM * SDIM;
        boff = coff = ((size_t)(bz >> 3)) * ((size_t)SDIM * DDIM) + (size_t)(bz & 7) * DK;
    }
    Ah += aoff; Al += aoff; Bh += boff; Bl += boff;

    const int row0 = blockIdx.y * BM;
    const int col0 = blockIdx.x * BN;
    const uint32_t sbase = smem_u32(smem);
    const int NC = K >> 6;

    auto load_stage = [&](int kc, int buf) {
        const uint32_t st = sbase + buf * STAGE;
        const int kp = kc << 6;
        constexpr int AU = BM * 8 / 256;
        #pragma unroll
        for (int i = 0; i < AU; i++) {
            int u = tid + i * 256;
            int r = u >> 3, c8 = u & 7;
            uint32_t d = st + sw128((uint32_t)r, (uint32_t)(c8 * 16));
            size_t go = (size_t)(row0 + r) * lda + kp + c8 * 8;
            cp16(d, Ah + go);
            cp16(d + ABYTES, Al + go);
        }
        if (!BTRANS) {
            constexpr int BU = BN * 8 / 256;
            #pragma unroll
            for (int i = 0; i < BU; i++) {
                int u = tid + i * 256;
                int r = u >> 3, c8 = u & 7;
                uint32_t d = st + 2 * ABYTES + sw128((uint32_t)r, (uint32_t)(c8 * 16));
                size_t go = (size_t)(col0 + r) * ldb + kp + c8 * 8;
                cp16(d, Bh + go);
                cp16(d + BBYTES, Bl + go);
            }
        } else {
            constexpr int NCH = BN * 2 / 16;       // 16B chunks per k-row
            constexpr int BU  = 64 * NCH / 256;
            #pragma unroll
            for (int i = 0; i < BU; i++) {
                int u = tid + i * 256;
                int r = u / NCH, c8 = u % NCH;
                uint32_t d = st + 2 * ABYTES + sw128((uint32_t)r, (uint32_t)(c8 * 16));
                size_t go = (size_t)(kp + r) * ldb + col0 + c8 * 8;
                cp16(d, Bh + go);
                cp16(d + BBYTES, Bl + go);
            }
        }
        asm volatile("cp.async.commit_group;" ::: "memory");
    };

    float acc[4][4][4];
    #pragma unroll
    for (int i = 0; i < 4; i++)
        #pragma unroll
        for (int j = 0; j < 4; j++)
            #pragma unroll
            for (int k2 = 0; k2 < 4; k2++) acc[i][j][k2] = 0.f;

    load_stage(0, 0);
    if (NC > 1) load_stage(1, 1);

    for (int kc = 0; kc < NC; kc++) {
        const int buf = kc & 1;
        if (kc < NC - 1) { asm volatile("cp.async.wait_group 1;" ::: "memory"); }
        else             { asm volatile("cp.async.wait_group 0;" ::: "memory"); }
        __syncthreads();
        const uint32_t sA = sbase + buf * STAGE;
        const uint32_t sB = sA + 2 * ABYTES;
        #pragma unroll
        for (int ks = 0; ks < 4; ks++) {
            uint32_t ah[4][4], al[4][4], bh[4][2], bl[4][2];
            int akb = ks * 32 + ((lane >> 4) << 4);
            #pragma unroll
            for (int mt = 0; mt < 4; mt++) {
                int ar = wm * 64 + mt * 16 + (lane & 15);
                uint32_t ad = sA + sw128((uint32_t)ar, (uint32_t)akb);
                ldsm4(ah[mt], ad);
                ldsm4(al[mt], ad + ABYTES);
            }
            if (!BTRANS) {
                int bkb = ks * 32 + ((lane >> 3) & 1) * 16;
                #pragma unroll
                for (int nt = 0; nt < 4; nt++) {
                    int br = wn * 32 + nt * 8 + (lane & 7);
                    uint32_t bd = sB + sw128((uint32_t)br, (uint32_t)bkb);
                    ldsm2(bh[nt], bd);
                    ldsm2(bl[nt], bd + BBYTES);
                }
            } else {
                int kr = ks * 16 + (lane & 15);
                #pragma unroll
                for (int nt = 0; nt < 4; nt++) {
                    int nb = (wn * 32 + nt * 8) * 2;
                    uint32_t bd = sB + sw128((uint32_t)kr, (uint32_t)nb);
                    ldsm2t(bh[nt], bd);
                    ldsm2t(bl[nt], bd + BBYTES);
                }
            }
            #pragma unroll
            for (int mt = 0; mt < 4; mt++)
                #pragma unroll
                for (int nt = 0; nt < 4; nt++) mma_bf16(acc[mt][nt], ah[mt], bh[nt]);
            #pragma unroll
            for (int mt = 0; mt < 4; mt++)
                #pragma unroll
                for (int nt = 0; nt < 4; nt++) mma_bf16(acc[mt][nt], ah[mt], bl[nt]);
            #pragma unroll
            for (int mt = 0; mt < 4; mt++)
                #pragma unroll
                for (int nt = 0; nt < 4; nt++) mma_bf16(acc[mt][nt], al[mt], bh[nt]);
        }
        __syncthreads();
        if (kc + 2 < NC) load_stage(kc + 2, buf);
    }

    // ---------------- epilogue ----------------
    const int grow = row0 + wm * 64;
    const int gcol = col0 + wn * 32;
    #pragma unroll
    for (int mt = 0; mt < 4; mt++) {
        #pragma unroll
        for (int half = 0; half < 2; half++) {
            int r = grow + mt * 16 + (lane >> 2) + half * 8;
            #pragma unroll
            for (int nt = 0; nt < 4; nt++) {
                int c = gcol + nt * 8 + (lane & 3) * 2;
                float v0 = acc[mt][nt][half * 2 + 0] * alpha;
                float v1 = acc[mt][nt][half * 2 + 1] * alpha;
                if (HASBIAS) { v0 += bias[c]; v1 += bias[c + 1]; }
                if (RMODE == 1) {
                    float2 rr = *(const float2*)(resid + (size_t)r * ldc + c);
                    v0 += rr.x; v1 += rr.y;
                } else if (RMODE == 2) {
                    float2 rr = *(const float2*)(resid + (size_t)(r & (SDIM - 1)) * ldc + c);
                    v0 += rr.x; v1 += rr.y;
                }
                if (RELU) { v0 = fmaxf(v0, 0.f); v1 = fmaxf(v1, 0.f); }
                if (WF32) {
                    *(float2*)(C + coff + (size_t)r * ldc + c) = make_float2(v0, v1);
                }
                if (WSPLIT) {
                    uint32_t hi, lo;
                    split2(v0, v1, hi, lo);
                    *(uint32_t*)(Ch + coff + (size_t)r * ldc + c) = hi;
                    *(uint32_t*)(Cl + coff + (size_t)r * ldc + c) = lo;
                }
            }
        }
    }
}

// ---------------- fp32 -> bf16 hi/lo split (x input only) ----------------
__global__ void split_kernel(const float* __restrict__ in, __nv_bfloat16* __restrict__ hi,
                             __nv_bfloat16* __restrict__ lo, int n4)
{
    int i = blockIdx.x * 256 + threadIdx.x;
    if (i >= n4) return;
    float4 v = ((const float4*)in)[i];
    uint32_t h0, l0, h1, l1;
    split2(v.x, v.y, h0, l0);
    split2(v.z, v.w, h1, l1);
    ((uint2*)hi)[i] = make_uint2(h0, h1);
    ((uint2*)lo)[i] = make_uint2(l0, l1);
}

// ---------------- transposed split: in (K x N) -> out (N x K) hi/lo ----------------
__global__ void tsplit_kernel(const float* __restrict__ in, __nv_bfloat16* __restrict__ oh,
                              __nv_bfloat16* __restrict__ ol, int K, int N,
                              size_t zin, size_t zout)
{
    __shared__ float tile[32][33];
    const float* inz = in + blockIdx.z * zin;
    __nv_bfloat16* ohz = oh + blockIdx.z * zout;
    __nv_bfloat16* olz = ol + blockIdx.z * zout;
    int tx = threadIdx.x, ty = threadIdx.y;
    int n = blockIdx.x * 32 + tx;
    #pragma unroll
    for (int j = 0; j < 4; j++) {
        int k = blockIdx.y * 32 + ty + j * 8;
        tile[ty + j * 8][tx] = inz[(size_t)k * N + n];
    }
    __syncthreads();
    int ko = blockIdx.y * 32 + tx;
    #pragma unroll
    for (int j = 0; j < 4; j++) {
        int no = blockIdx.x * 32 + ty + j * 8;
        float v = tile[tx][ty + j * 8];
        __nv_bfloat16 h = __float2bfloat16(v);
        __nv_bfloat16 l = __float2bfloat16(v - __bfloat162float(h));
        ohz[(size_t)no * K + ko] = h;
        olz[(size_t)no * K + ko] = l;
    }
}

// ---------------- relative position bias ----------------
__global__ void posbias_kernel(const float* __restrict__ rel_emb, float* __restrict__ pb) {
    int s = blockIdx.x;
    int d = threadIdx.x;
    float acc = 0.f;
    int c0 = s - 31; if (c0 < 0) c0 = 0;
    acc += (float)c0 * rel_emb[0 * DDIM + d];
    int c64 = 480 - s; if (c64 < 0) c64 = 0;
    acc += (float)c64 * rel_emb[64 * DDIM + d];
    #pragma unroll 1
    for (int r = 1; r < 64; r++) {
        int qq = s + r - 32;
        if (qq >= 0 && qq < SDIM) acc += rel_emb[r * DDIM + d];
    }
    pb[s * DDIM + d] = acc * (1.0f / (float)SDIM);
}

// ---------------- block reduce helpers (128 threads) ----------------
__device__ __forceinline__ float blockReduceSum128(float v, float* shm) {
    #pragma unroll
    for (int o = 16; o > 0; o >>= 1) v += __shfl_xor_sync(0xffffffffu, v, o);
    if ((threadIdx.x & 31) == 0) shm[threadIdx.x >> 5] = v;
    __syncthreads();
    v = shm[0] + shm[1] + shm[2] + shm[3];
    __syncthreads();
    return v;
}
__device__ __forceinline__ float blockReduceMax128(float v, float* shm) {
    #pragma unroll
    for (int o = 16; o > 0; o >>= 1) v = fmaxf(v, __shfl_xor_sync(0xffffffffu, v, o));
    if ((threadIdx.x & 31) == 0) shm[threadIdx.x >> 5] = v;
    __syncthreads();
    v = fmaxf(fmaxf(shm[0], shm[1]), fmaxf(shm[2], shm[3]));
    __syncthreads();
    return v;
}

// ---------------- softmax over 512 rows -> bf16 hi/lo ----------------
__global__ void softmax512(const float* __restrict__ sc,
                           __nv_bfloat16* __restrict__ ph, __nv_bfloat16* __restrict__ pl)
{
    __shared__ float shm[4];
    size_t row = blockIdx.x;
    const float* p = sc + row * SDIM;
    int t = threadIdx.x;  // 128
    float4 v = ((const float4*)p)[t];
    float m = fmaxf(fmaxf(v.x, v.y), fmaxf(v.z, v.w));
    m = blockReduceMax128(m, shm);
    v.x = __expf(v.x - m); v.y = __expf(v.y - m);
    v.z = __expf(v.z - m); v.w = __expf(v.w - m);
    float s = v.x + v.y + v.z + v.w;
    s = blockReduceSum128(s, shm);
    float inv = 1.0f / s;
    v.x *= inv; v.y *= inv; v.z *= inv; v.w *= inv;
    uint32_t h0, l0, h1, l1;
    split2(v.x, v.y, h0, l0);
    split2(v.z, v.w, h1, l1);
    ((uint2*)(ph + row * SDIM))[t] = make_uint2(h0, h1);
    ((uint2*)(pl + row * SDIM))[t] = make_uint2(l0, l1);
}

// ---------------- layernorm over 512 rows -> fp32 + bf16 hi/lo ----------------
__global__ void layernorm512(const float* __restrict__ in, const float* __restrict__ g,
                             const float* __restrict__ bta, float* __restrict__ out,
                             __nv_bfloat16* __restrict__ oh, __nv_bfloat16* __restrict__ ol)
{
    __shared__ float shm[4];
    size_t row = blockIdx.x;
    const float* p = in + row * DDIM;
    int t = threadIdx.x;  // 128
    float4 v = ((const float4*)p)[t];
    float s = v.x + v.y + v.z + v.w;
    s = blockReduceSum128(s, shm);
    float mu = s * (1.0f / (float)DDIM);
    float dx = v.x - mu, dy = v.y - mu, dz = v.z - mu, dw = v.w - mu;
    float sq = dx * dx + dy * dy + dz * dz + dw * dw;
    sq = blockReduceSum128(sq, shm);
    float var = sq * (1.0f / (float)DDIM);
    float inv = rsqrtf(var + 1e-5f);
    float4 gg = ((const float4*)g)[t];
    float4 bb = ((const float4*)bta)[t];
    float4 o;
    o.x = dx * inv * gg.x + bb.x;
    o.y = dy * inv * gg.y + bb.y;
    o.z = dz * inv * gg.z + bb.z;
    o.w = dw * inv * gg.w + bb.w;
    ((float4*)(out + row * DDIM))[t] = o;
    uint32_t h0, l0, h1, l1;
    split2(o.x, o.y, h0, l0);
    split2(o.z, o.w, h1, l1);
    ((uint2*)(oh + row * DDIM))[t] = make_uint2(h0, h1);
    ((uint2*)(ol + row * DDIM))[t] = make_uint2(l0, l1);
}

// ---------------- final projection ----------------
__global__ void outproj(const float* __restrict__ h, const float* __restrict__ W,
                        const float* __restrict__ ob, float* __restrict__ out)
{
    __shared__ float shm[4];
    size_t row = blockIdx.x;
    int t = threadIdx.x;
    float4 v = ((const float4*)(h + row * DDIM))[t];
    float4 w = ((const float4*)W)[t];
    float s = v.x * w.x + v.y * w.y + v.z * w.z + v.w * w.w;
    s = blockReduceSum128(s, shm);
    if (t == 0) out[row] = s + ob[0];
}

// ---------------- config aliases ----------------
// dense: BM=128,BN=128, warps 2x4.  ctx: BM=256,BN=64, warps 4x2 (B via ldmatrix.trans).
#define DENSE_SMEM (2 * (2 * 128 * 128 + 2 * 128 * 128))          // 131072
#define CTX_SMEM   (2 * (2 * 256 * 128 + 2 * 64 * 64 * 2))        // 163840

// instantiation helpers
static constexpr int M0 = 0, M1 = 1, M2 = 2;

extern "C" void kernel_launch(void* const* d_in, const int* in_sizes, int n_in,
                              void* d_out, int out_size)
{
    (void)in_sizes; (void)n_in; (void)out_size;
    const float* x       = (const float*)d_in[0];
    const float* in_W    = (const float*)d_in[1];
    const float* in_b    = (const float*)d_in[2];
    const float* rel_emb = (const float*)d_in[3];
    const float* qkvo_W  = (const float*)d_in[4];
    const float* qkvo_b  = (const float*)d_in[5];
    const float* ln_g    = (const float*)d_in[6];
    const float* ln_b    = (const float*)d_in[7];
    const float* ff_W1   = (const float*)d_in[8];
    const float* ff_b1   = (const float*)d_in[9];
    const float* ff_W2   = (const float*)d_in[10];
    const float* ff_b2   = (const float*)d_in[11];
    const float* out_W   = (const float*)d_in[12];
    const float* out_b   = (const float*)d_in[13];

    float *h, *h1, *tbuf, *sc, *pb;
    __nv_bfloat16 *xh, *xl, *ah, *al, *fh, *fl, *qh, *ql, *kh, *kl, *vh, *vl, *ph, *pl, *wh, *wl;
    cudaGetSymbolAddress((void**)&h,    g_h);
    cudaGetSymbolAddress((void**)&h1,   g_h1);
    cudaGetSymbolAddress((void**)&tbuf, g_t);
    cudaGetSymbolAddress((void**)&sc,   g_sc);
    cudaGetSymbolAddress((void**)&pb,   g_pb);
    cudaGetSymbolAddress((void**)&xh,   g_xh);
    cudaGetSymbolAddress((void**)&xl,   g_xl);
    cudaGetSymbolAddress((void**)&ah,   g_ah);
    cudaGetSymbolAddress((void**)&al,   g_al);
    cudaGetSymbolAddress((void**)&fh,   g_fh);
    cudaGetSymbolAddress((void**)&fl,   g_fl);
    cudaGetSymbolAddress((void**)&qh,   g_qh);
    cudaGetSymbolAddress((void**)&ql,   g_ql);
    cudaGetSymbolAddress((void**)&kh,   g_kh);
    cudaGetSymbolAddress((void**)&kl,   g_kl);
    cudaGetSymbolAddress((void**)&vh,   g_vh);
    cudaGetSymbolAddress((void**)&vl,   g_vl);
    cudaGetSymbolAddress((void**)&ph,   g_ph);
    cudaGetSymbolAddress((void**)&pl,   g_pl);
    cudaGetSymbolAddress((void**)&wh,   g_wh);
    cudaGetSymbolAddress((void**)&wl,   g_wl);

    // kernel instantiations
    auto k_inproj = mma_gemm<128,128,2,4, M0,false, false,2,true,  true, true >;
    auto k_proj_s = mma_gemm<128,128,2,4, M0,false, false,0,true,  false,true >;  // QKV -> split only
    auto k_scores = mma_gemm<128,128,2,4, M1,false, false,0,false, true, false>;
    auto k_ctx    = mma_gemm<256, 64,4,2, M2,true,  false,0,false, false,true >;
    auto k_res    = mma_gemm<128,128,2,4, M0,false, false,1,true,  true, false>;  // o-proj / FF2
    auto k_ff1    = mma_gemm<128,128,2,4, M0,false, true, 0,true,  false,true >;

    cudaFuncSetAttribute(k_inproj, cudaFuncAttributeMaxDynamicSharedMemorySize, DENSE_SMEM);
    cudaFuncSetAttribute(k_proj_s, cudaFuncAttributeMaxDynamicSharedMemorySize, DENSE_SMEM);
    cudaFuncSetAttribute(k_scores, cudaFuncAttributeMaxDynamicSharedMemorySize, DENSE_SMEM);
    cudaFuncSetAttribute(k_ctx,    cudaFuncAttributeMaxDynamicSharedMemorySize, CTX_SMEM);
    cudaFuncSetAttribute(k_res,    cudaFuncAttributeMaxDynamicSharedMemorySize, DENSE_SMEM);
    cudaFuncSetAttribute(k_ff1,    cudaFuncAttributeMaxDynamicSharedMemorySize, DENSE_SMEM);

    // ---- weight transpose+split ----
    tsplit_kernel<<<dim3(512 / 32, 64 / 32, 1), dim3(32, 8)>>>(
        in_W, wh + WT_IN, wl + WT_IN, 64, 512, 0, 0);
    tsplit_kernel<<<dim3(16, 16, 24), dim3(32, 8)>>>(
        qkvo_W, wh + WT_QKVO, wl + WT_QKVO, 512, 512,
        (size_t)512 * 512, (size_t)512 * 512);
    tsplit_kernel<<<dim3(2048 / 32, 512 / 32, 6), dim3(32, 8)>>>(
        ff_W1, wh + WT_W1, wl + WT_W1, 512, 2048,
        (size_t)512 * 2048, (size_t)512 * 2048);
    tsplit_kernel<<<dim3(512 / 32, 2048 / 32, 6), dim3(32, 8)>>>(
        ff_W2, wh + WT_W2, wl + WT_W2, 2048, 512,
        (size_t)2048 * 512, (size_t)2048 * 512);

    // ---- position bias & input projection ----
    posbias_kernel<<<SDIM, DDIM>>>(rel_emb, pb);
    split_kernel<<<(MSROWS * 64 / 4 + 255) / 256, 256>>>(x, xh, xl, MSROWS * 64 / 4);
    // h = x @ in_W + in_b + pb  (fp32 h + split -> ah/al)
    k_inproj<<<dim3(4, 64), 256, DENSE_SMEM>>>(
        xh, xl, 64, wh + WT_IN, wl + WT_IN, 64, in_b, pb, h, ah, al, DDIM, 64, 1.0f);

    for (int l = 0; l < LNUM; l++) {
        const __nv_bfloat16* Wq_h = wh + WT_QKVO + ((size_t)l * 4 + 0) * 512 * 512;
        const __nv_bfloat16* Wq_l = wl + WT_QKVO + ((size_t)l * 4 + 0) * 512 * 512;
        const __nv_bfloat16* Wk_h = wh + WT_QKVO + ((size_t)l * 4 + 1) * 512 * 512;
        const __nv_bfloat16* Wk_l = wl + WT_QKVO + ((size_t)l * 4 + 1) * 512 * 512;
        const __nv_bfloat16* Wv_h = wh + WT_QKVO + ((size_t)l * 4 + 2) * 512 * 512;
        const __nv_bfloat16* Wv_l = wl + WT_QKVO + ((size_t)l * 4 + 2) * 512 * 512;
        const __nv_bfloat16* Wo_h = wh + WT_QKVO + ((size_t)l * 4 + 3) * 512 * 512;
        const __nv_bfloat16* Wo_l = wl + WT_QKVO + ((size_t)l * 4 + 3) * 512 * 512;
        const __nv_bfloat16* W1h = wh + WT_W1 + (size_t)l * 2048 * 512;
        const __nv_bfloat16* W1l = wl + WT_W1 + (size_t)l * 2048 * 512;
        const __nv_bfloat16* W2h = wh + WT_W2 + (size_t)l * 512 * 2048;
        const __nv_bfloat16* W2l = wl + WT_W2 + (size_t)l * 512 * 2048;
        const float* bq  = qkvo_b + ((size_t)l * 4 + 0) * DDIM;
        const float* bk  = qkvo_b + ((size_t)l * 4 + 1) * DDIM;
        const float* bv  = qkvo_b + ((size_t)l * 4 + 2) * DDIM;
        const float* bo  = qkvo_b + ((size_t)l * 4 + 3) * DDIM;
        const float* g0  = ln_g + ((size_t)l * 2 + 0) * DDIM;
        const float* b0  = ln_b + ((size_t)l * 2 + 0) * DDIM;
        const float* g1  = ln_g + ((size_t)l * 2 + 1) * DDIM;
        const float* b1l = ln_b + ((size_t)l * 2 + 1) * DDIM;
        const float* fb1 = ff_b1 + (size_t)l * FDIM;
        const float* fb2 = ff_b2 + (size_t)l * DDIM;

        dim3 gp(4, 64);
        // QKV projections: input ah/al (h split), outputs bf16 split directly
        k_proj_s<<<gp, 256, DENSE_SMEM>>>(ah, al, 512, Wq_h, Wq_l, 512, bq, nullptr,
                                          nullptr, qh, ql, DDIM, 512, 1.0f);
        k_proj_s<<<gp, 256, DENSE_SMEM>>>(ah, al, 512, Wk_h, Wk_l, 512, bk, nullptr,
                                          nullptr, kh, kl, DDIM, 512, 1.0f);
        k_proj_s<<<gp, 256, DENSE_SMEM>>>(ah, al, 512, Wv_h, Wv_l, 512, bv, nullptr,
                                          nullptr, vh, vl, DDIM, 512, 1.0f);

        // scores = (Q K^T)/8  (per head), softmax -> P hi/lo
        k_scores<<<dim3(4, 4, BDIM * HDIM), 256, DENSE_SMEM>>>(
            qh, ql, 512, kh, kl, 512, nullptr, nullptr, sc, nullptr, nullptr,
            SDIM, 64, 0.125f);
        softmax512<<<BDIM * HDIM * SDIM, 128>>>(sc, ph, pl);

        // ctx = P @ V  -> split into ah/al (overwrites h-split; safe, already consumed)
        k_ctx<<<dim3(1, 2, BDIM * HDIM), 256, CTX_SMEM>>>(
            ph, pl, 512, vh, vl, 512, nullptr, nullptr, nullptr, ah, al, DDIM, 512, 1.0f);

        // o-proj + residual(h) -> tbuf (fp32), then LN1 -> h1 fp32 + ah/al split
        k_res<<<gp, 256, DENSE_SMEM>>>(ah, al, 512, Wo_h, Wo_l, 512, bo, h,
                                       tbuf, nullptr, nullptr, DDIM, 512, 1.0f);
        layernorm512<<<MSROWS, 128>>>(tbuf, g0, b0, h1, ah, al);

        // FF1 (relu) -> fh/fl split only
        k_ff1<<<dim3(16, 64), 256, DENSE_SMEM>>>(ah, al, 512, W1h, W1l, 512, fb1, nullptr,
                                                 nullptr, fh, fl, FDIM, 512, 1.0f);
        // FF2 + residual(h1) -> tbuf, then LN2 -> h fp32 + ah/al split (next layer input)
        k_res<<<gp, 256, DENSE_SMEM>>>(fh, fl, 2048, W2h, W2l, 2048, fb2, h1,
                                       tbuf, nullptr, nullptr, DDIM, 2048, 1.0f);
        layernorm512<<<MSROWS, 128>>>(tbuf, g1, b1l, h, ah, al);
    }

    outproj<<<MSROWS, 128>>>(h, out_W, out_b, (float*)d_out);
}

// round 6
// speedup vs baseline: 3.0753x; 1.0932x over previous
#include <cuda_runtime.h>
#include <cuda_bf16.h>
#include <cstdint>
#include <cstddef>

// ---------------- problem constants ----------------
#define SDIM   512
#define DDIM   512
#define BDIM   16
#define HDIM   8
#define LNUM   6
#define FDIM   2048
#define MSROWS (BDIM * SDIM)   // 8192
#define DK     64

// ---------------- low-level helpers (sm_80+ PTX only) ----------------
__device__ __forceinline__ uint32_t smem_u32(const void* p) {
    uint32_t a;
    asm("{ .reg .u64 t; cvta.to.shared.u64 t, %1; cvt.u32.u64 %0, t; }" : "=r"(a) : "l"(p));
    return a;
}
__device__ __forceinline__ void cp16(uint32_t dst, const void* src) {
    asm volatile("cp.async.cg.shared.global [%0], [%1], 16;" :: "r"(dst), "l"(src));
}
__device__ __forceinline__ void ldsm4(uint32_t a[4], uint32_t addr) {
    asm volatile("ldmatrix.sync.aligned.m8n8.x4.shared.b16 {%0,%1,%2,%3}, [%4];"
        : "=r"(a[0]), "=r"(a[1]), "=r"(a[2]), "=r"(a[3]) : "r"(addr));
}
__device__ __forceinline__ void ldsm2(uint32_t a[2], uint32_t addr) {
    asm volatile("ldmatrix.sync.aligned.m8n8.x2.shared.b16 {%0,%1}, [%2];"
        : "=r"(a[0]), "=r"(a[1]) : "r"(addr));
}
__device__ __forceinline__ void ldsm2t(uint32_t a[2], uint32_t addr) {
    asm volatile("ldmatrix.sync.aligned.m8n8.x2.trans.shared.b16 {%0,%1}, [%2];"
        : "=r"(a[0]), "=r"(a[1]) : "r"(addr));
}
__device__ __forceinline__ void mma_bf16(float c[4], const uint32_t a[4], const uint32_t b[2]) {
    asm volatile(
        "mma.sync.aligned.m16n8k16.row.col.f32.bf16.bf16.f32 "
        "{%0,%1,%2,%3}, {%4,%5,%6,%7}, {%8,%9}, {%0,%1,%2,%3};"
        : "+f"(c[0]), "+f"(c[1]), "+f"(c[2]), "+f"(c[3])
        : "r"(a[0]), "r"(a[1]), "r"(a[2]), "r"(a[3]), "r"(b[0]), "r"(b[1]));
}
__device__ __forceinline__ uint32_t sw128(uint32_t row, uint32_t byte_in_row) {
    return row * 128u + (byte_in_row ^ ((row & 7u) << 4));
}
__device__ __forceinline__ void split2(float a, float b, uint32_t& hi, uint32_t& lo) {
    __nv_bfloat16 ha = __float2bfloat16(a), hb = __float2bfloat16(b);
    float ra = a - __bfloat162float(ha), rb = b - __bfloat162float(hb);
    hi = (uint32_t)__bfloat16_as_ushort(ha) | ((uint32_t)__bfloat16_as_ushort(hb) << 16);
    lo = (uint32_t)__bfloat16_as_ushort(__float2bfloat16(ra)) |
         ((uint32_t)__bfloat16_as_ushort(__float2bfloat16(rb)) << 16);
}

// ---------------- scratch (static device globals) ----------------
__device__ float g_h  [MSROWS * DDIM];
__device__ float g_h1 [MSROWS * DDIM];
__device__ float g_t  [MSROWS * DDIM];
__device__ float g_pb [SDIM * DDIM];

__device__ __nv_bfloat16 g_xh[MSROWS * 64];
__device__ __nv_bfloat16 g_xl[MSROWS * 64];
__device__ __nv_bfloat16 g_ah[MSROWS * DDIM];
__device__ __nv_bfloat16 g_al[MSROWS * DDIM];
__device__ __nv_bfloat16 g_fh[MSROWS * FDIM];
__device__ __nv_bfloat16 g_fl[MSROWS * FDIM];
__device__ __nv_bfloat16 g_qkh[(size_t)MSROWS * 1536];   // fused QKV split
__device__ __nv_bfloat16 g_qkl[(size_t)MSROWS * 1536];

// transposed weights (hi/lo)
#define WT_IN    0
#define WT_QKVO  (512 * 64)
#define WT_W1    (WT_QKVO + 24 * 512 * 512)
#define WT_W2    (WT_W1 + 6 * 2048 * 512)
#define WT_TOTAL (WT_W2 + 6 * 512 * 2048)
__device__ __nv_bfloat16 g_wh[WT_TOTAL];
__device__ __nv_bfloat16 g_wl[WT_TOTAL];

// ---------------- dense MMA GEMM (bf16 hi/lo 3-pass) ----------------
#define DBM 128
#define DBN 128
#define ABYTES (DBM * 128)
#define BBYTES (DBN * 128)
#define STAGE  (2 * ABYTES + 2 * BBYTES)
#define DENSE_SMEM (2 * STAGE)

template<bool RELU, int RMODE, bool HASBIAS, bool WF32, bool WSPLIT>
__global__ void __launch_bounds__(256, 1)
mma_gemm(const __nv_bfloat16* __restrict__ Ah, const __nv_bfloat16* __restrict__ Al, int lda,
         const __nv_bfloat16* __restrict__ Bh, const __nv_bfloat16* __restrict__ Bl, int ldb,
         const float* __restrict__ bias, const float* __restrict__ resid,
         float* __restrict__ C, __nv_bfloat16* __restrict__ Ch, __nv_bfloat16* __restrict__ Cl,
         int ldc, int K, float alpha)
{
    extern __shared__ char smem[];
    const int tid  = threadIdx.x;
    const int wid  = tid >> 5;
    const int lane = tid & 31;
    const int wm   = wid >> 2;          // 2 x 4 warp grid
    const int wn   = wid & 3;

    const int row0 = blockIdx.y * DBM;
    const int col0 = blockIdx.x * DBN;
    const uint32_t sbase = smem_u32(smem);
    const int NC = K >> 6;

    auto load_stage = [&](int kc, int buf) {
        const uint32_t st = sbase + buf * STAGE;
        const int kp = kc << 6;
        #pragma unroll
        for (int i = 0; i < 4; i++) {
            int u = tid + i * 256;
            int r = u >> 3, c8 = u & 7;
            uint32_t d = st + sw128((uint32_t)r, (uint32_t)(c8 * 16));
            size_t go = (size_t)(row0 + r) * lda + kp + c8 * 8;
            cp16(d, Ah + go);
            cp16(d + ABYTES, Al + go);
        }
        #pragma unroll
        for (int i = 0; i < 4; i++) {
            int u = tid + i * 256;
            int r = u >> 3, c8 = u & 7;
            uint32_t d = st + 2 * ABYTES + sw128((uint32_t)r, (uint32_t)(c8 * 16));
            size_t go = (size_t)(col0 + r) * ldb + kp + c8 * 8;
            cp16(d, Bh + go);
            cp16(d + BBYTES, Bl + go);
        }
        asm volatile("cp.async.commit_group;" ::: "memory");
    };

    float acc[4][4][4];
    #pragma unroll
    for (int i = 0; i < 4; i++)
        #pragma unroll
        for (int j = 0; j < 4; j++)
            #pragma unroll
            for (int k2 = 0; k2 < 4; k2++) acc[i][j][k2] = 0.f;

    load_stage(0, 0);
    if (NC > 1) load_stage(1, 1);

    for (int kc = 0; kc < NC; kc++) {
        const int buf = kc & 1;
        if (kc < NC - 1) { asm volatile("cp.async.wait_group 1;" ::: "memory"); }
        else             { asm volatile("cp.async.wait_group 0;" ::: "memory"); }
        __syncthreads();
        const uint32_t sA = sbase + buf * STAGE;
        const uint32_t sB = sA + 2 * ABYTES;
        #pragma unroll
        for (int ks = 0; ks < 4; ks++) {
            uint32_t ah[4][4], al[4][4], bh[4][2], bl[4][2];
            int akb = ks * 32 + ((lane >> 4) << 4);
            #pragma unroll
            for (int mt = 0; mt < 4; mt++) {
                int ar = wm * 64 + mt * 16 + (lane & 15);
                uint32_t ad = sA + sw128((uint32_t)ar, (uint32_t)akb);
                ldsm4(ah[mt], ad);
                ldsm4(al[mt], ad + ABYTES);
            }
            int bkb = ks * 32 + ((lane >> 3) & 1) * 16;
            #pragma unroll
            for (int nt = 0; nt < 4; nt++) {
                int br = wn * 32 + nt * 8 + (lane & 7);
                uint32_t bd = sB + sw128((uint32_t)br, (uint32_t)bkb);
                ldsm2(bh[nt], bd);
                ldsm2(bl[nt], bd + BBYTES);
            }
            #pragma unroll
            for (int mt = 0; mt < 4; mt++)
                #pragma unroll
                for (int nt = 0; nt < 4; nt++) mma_bf16(acc[mt][nt], ah[mt], bh[nt]);
            #pragma unroll
            for (int mt = 0; mt < 4; mt++)
                #pragma unroll
                for (int nt = 0; nt < 4; nt++) mma_bf16(acc[mt][nt], ah[mt], bl[nt]);
            #pragma unroll
            for (int mt = 0; mt < 4; mt++)
                #pragma unroll
                for (int nt = 0; nt < 4; nt++) mma_bf16(acc[mt][nt], al[mt], bh[nt]);
        }
        __syncthreads();
        if (kc + 2 < NC) load_stage(kc + 2, buf);
    }

    const int grow = row0 + wm * 64;
    const int gcol = col0 + wn * 32;
    #pragma unroll
    for (int mt = 0; mt < 4; mt++) {
        #pragma unroll
        for (int half = 0; half < 2; half++) {
            int r = grow + mt * 16 + (lane >> 2) + half * 8;
            #pragma unroll
            for (int nt = 0; nt < 4; nt++) {
                int c = gcol + nt * 8 + (lane & 3) * 2;
                float v0 = acc[mt][nt][half * 2 + 0] * alpha;
                float v1 = acc[mt][nt][half * 2 + 1] * alpha;
                if (HASBIAS) { v0 += bias[c]; v1 += bias[c + 1]; }
                if (RMODE == 1) {
                    float2 rr = *(const float2*)(resid + (size_t)r * ldc + c);
                    v0 += rr.x; v1 += rr.y;
                } else if (RMODE == 2) {
                    float2 rr = *(const float2*)(resid + (size_t)(r & (SDIM - 1)) * ldc + c);
                    v0 += rr.x; v1 += rr.y;
                }
                if (RELU) { v0 = fmaxf(v0, 0.f); v1 = fmaxf(v1, 0.f); }
                if (WF32) {
                    *(float2*)(C + (size_t)r * ldc + c) = make_float2(v0, v1);
                }
                if (WSPLIT) {
                    uint32_t hi, lo;
                    split2(v0, v1, hi, lo);
                    *(uint32_t*)(Ch + (size_t)r * ldc + c) = hi;
                    *(uint32_t*)(Cl + (size_t)r * ldc + c) = lo;
                }
            }
        }
    }
}

// ---------------- fused flash attention ----------------
// grid (B*H, S/128), 256 threads. QKV buffer: (B*S, 1536) hi/lo bf16.
// Per CTA: q-tile 128 rows, loop 4 kv-blocks of 128.
#define FA_QH   0
#define FA_QL   16384
#define FA_K0   32768            // each K buf: hi 16K + lo 16K
#define FA_VH   98304
#define FA_VL   114688
#define FA_PHA  131072
#define FA_PHB  147456
#define FA_PLA  163840
#define FA_PLB  180224
#define FA_STATS 196608
#define FA_SMEM (196608 + 2560)

__global__ void __launch_bounds__(256, 1)
flash_attn(const __nv_bfloat16* __restrict__ Xh, const __nv_bfloat16* __restrict__ Xl,
           __nv_bfloat16* __restrict__ Oh, __nv_bfloat16* __restrict__ Ol)
{
    extern __shared__ char smem[];
    const uint32_t sbase = smem_u32(smem);
    float* m_s  = (float*)(smem + FA_STATS);
    float* l_s  = m_s + 128;
    float* sc_s = m_s + 256;
    float* sred = m_s + 384;   // [256]

    const int tid = threadIdx.x, wid = tid >> 5, lane = tid & 31;
    const int wm = wid >> 1, wn = wid & 1;       // 4 x 2 warp grid
    const int z = blockIdx.x;
    const int b = z >> 3, hh = z & 7;
    const int q0 = blockIdx.y * 128;
    const size_t rowb = (size_t)b * SDIM;
    const int qcol = hh * 64, kcol = 512 + hh * 64, vcol = 1024 + hh * 64;

    auto load64 = [&](uint32_t dh, uint32_t dl, size_t grow, int gcol) {
        #pragma unroll
        for (int i = 0; i < 4; i++) {
            int u = tid + i * 256;
            int r = u >> 3, c8 = u & 7;
            uint32_t off = sw128((uint32_t)r, (uint32_t)(c8 * 16));
            size_t go = (grow + r) * 1536 + gcol + c8 * 8;
            cp16(dh + off, Xh + go);
            cp16(dl + off, Xl + go);
        }
    };

    // prologue: Q + K0 (group), V0 (group)
    load64(sbase + FA_QH, sbase + FA_QL, rowb + q0, qcol);
    load64(sbase + FA_K0, sbase + FA_K0 + 16384, rowb, kcol);
    asm volatile("cp.async.commit_group;" ::: "memory");
    load64(sbase + FA_VH, sbase + FA_VL, rowb, vcol);
    asm volatile("cp.async.commit_group;" ::: "memory");

    if (tid < 128) { m_s[tid] = -1e30f; l_s[tid] = 0.f; }

    float acco[2][4][4];
    #pragma unroll
    for (int mt = 0; mt < 2; mt++)
        #pragma unroll
        for (int nt = 0; nt < 4; nt++)
            #pragma unroll
            for (int j = 0; j < 4; j++) acco[mt][nt][j] = 0.f;

    for (int kb = 0; kb < 4; kb++) {
        // K(kb) ready (V(kb) may still be in flight)
        asm volatile("cp.async.wait_group 1;" ::: "memory");
        __syncthreads();

        // ---- S = (Q K^T) / 8 ----
        float accs[2][8][4];
        #pragma unroll
        for (int mt = 0; mt < 2; mt++)
            #pragma unroll
            for (int nt = 0; nt < 8; nt++)
                #pragma unroll
                for (int j = 0; j < 4; j++) accs[mt][nt][j] = 0.f;

        const uint32_t sK = sbase + FA_K0 + (uint32_t)(kb & 1) * 32768u;
        #pragma unroll
        for (int ks = 0; ks < 4; ks++) {
            uint32_t qh4[2][4], ql4[2][4], kh2[8][2], kl2[8][2];
            int akb = ks * 32 + ((lane >> 4) << 4);
            #pragma unroll
            for (int mt = 0; mt < 2; mt++) {
                int r = wm * 32 + mt * 16 + (lane & 15);
                uint32_t off = sw128((uint32_t)r, (uint32_t)akb);
                ldsm4(qh4[mt], sbase + FA_QH + off);
                ldsm4(ql4[mt], sbase + FA_QL + off);
            }
            int bkb = ks * 32 + ((lane >> 3) & 1) * 16;
            #pragma unroll
            for (int nt = 0; nt < 8; nt++) {
                int br = wn * 64 + nt * 8 + (lane & 7);
                uint32_t off = sw128((uint32_t)br, (uint32_t)bkb);
                ldsm2(kh2[nt], sK + off);
                ldsm2(kl2[nt], sK + 16384 + off);
            }
            #pragma unroll
            for (int mt = 0; mt < 2; mt++)
                #pragma unroll
                for (int nt = 0; nt < 8; nt++) mma_bf16(accs[mt][nt], qh4[mt], kh2[nt]);
            #pragma unroll
            for (int mt = 0; mt < 2; mt++)
                #pragma unroll
                for (int nt = 0; nt < 8; nt++) mma_bf16(accs[mt][nt], qh4[mt], kl2[nt]);
            #pragma unroll
            for (int mt = 0; mt < 2; mt++)
                #pragma unroll
                for (int nt = 0; nt < 8; nt++) mma_bf16(accs[mt][nt], ql4[mt], kh2[nt]);
        }
        #pragma unroll
        for (int mt = 0; mt < 2; mt++)
            #pragma unroll
            for (int nt = 0; nt < 8; nt++)
                #pragma unroll
                for (int j = 0; j < 4; j++) accs[mt][nt][j] *= 0.125f;

        // ---- row max (partial -> cross-lane -> cross-warp) ----
        float pm[2][2];
        #pragma unroll
        for (int mt = 0; mt < 2; mt++)
            #pragma unroll
            for (int half = 0; half < 2; half++) {
                float v = -1e30f;
                #pragma unroll
                for (int nt = 0; nt < 8; nt++) {
                    v = fmaxf(v, accs[mt][nt][half * 2 + 0]);
                    v = fmaxf(v, accs[mt][nt][half * 2 + 1]);
                }
                v = fmaxf(v, __shfl_xor_sync(0xffffffffu, v, 1));
                v = fmaxf(v, __shfl_xor_sync(0xffffffffu, v, 2));
                pm[mt][half] = v;
            }
        if ((lane & 3) == 0) {
            #pragma unroll
            for (int mt = 0; mt < 2; mt++)
                #pragma unroll
                for (int half = 0; half < 2; half++) {
                    int r = wm * 32 + mt * 16 + (lane >> 2) + half * 8;
                    sred[wn * 128 + r] = pm[mt][half];
                }
        }
        __syncthreads();
        if (tid < 128) {
            float mo = m_s[tid];
            float mn = fmaxf(mo, fmaxf(sred[tid], sred[128 + tid]));
            m_s[tid] = mn;
            sc_s[tid] = __expf(mo - mn);
        }
        __syncthreads();

        // ---- P = exp(S - m), store to smem (hi/lo), row sums ----
        float ps[2][2] = {{0.f, 0.f}, {0.f, 0.f}};
        #pragma unroll
        for (int mt = 0; mt < 2; mt++)
            #pragma unroll
            for (int half = 0; half < 2; half++) {
                int r = wm * 32 + mt * 16 + (lane >> 2) + half * 8;
                float mr = m_s[r];
                #pragma unroll
                for (int nt = 0; nt < 8; nt++) {
                    float p0 = __expf(accs[mt][nt][half * 2 + 0] - mr);
                    float p1 = __expf(accs[mt][nt][half * 2 + 1] - mr);
                    ps[mt][half] += p0 + p1;
                    uint32_t hi, lo;
                    split2(p0, p1, hi, lo);
                    int c = nt * 8 + (lane & 3) * 2;   // 0..63 within half (wn = half)
                    uint32_t off = sw128((uint32_t)r, (uint32_t)(c * 2));
                    *(uint32_t*)(smem + (wn ? FA_PHB : FA_PHA) + off) = hi;
                    *(uint32_t*)(smem + (wn ? FA_PLB : FA_PLA) + off) = lo;
                }
            }
        #pragma unroll
        for (int mt = 0; mt < 2; mt++)
            #pragma unroll
            for (int half = 0; half < 2; half++) {
                float v = ps[mt][half];
                v += __shfl_xor_sync(0xffffffffu, v, 1);
                v += __shfl_xor_sync(0xffffffffu, v, 2);
                ps[mt][half] = v;
            }
        if ((lane & 3) == 0) {
            #pragma unroll
            for (int mt = 0; mt < 2; mt++)
                #pragma unroll
                for (int half = 0; half < 2; half++) {
                    int r = wm * 32 + mt * 16 + (lane >> 2) + half * 8;
                    sred[wn * 128 + r] = ps[mt][half];
                }
        }
        __syncthreads();
        if (tid < 128) l_s[tid] = l_s[tid] * sc_s[tid] + sred[tid] + sred[128 + tid];

        // prefetch next K block
        if (kb < 3) {
            load64(sbase + FA_K0 + (uint32_t)((kb + 1) & 1) * 32768u,
                   sbase + FA_K0 + (uint32_t)((kb + 1) & 1) * 32768u + 16384,
                   rowb + (kb + 1) * 128, kcol);
            asm volatile("cp.async.commit_group;" ::: "memory");
            asm volatile("cp.async.wait_group 1;" ::: "memory");   // V(kb) done
        } else {
            asm volatile("cp.async.wait_group 0;" ::: "memory");
        }
        __syncthreads();

        // ---- O = O*scale + P V ----
        #pragma unroll
        for (int mt = 0; mt < 2; mt++)
            #pragma unroll
            for (int half = 0; half < 2; half++) {
                int r = wm * 32 + mt * 16 + (lane >> 2) + half * 8;
                float s = sc_s[r];
                #pragma unroll
                for (int nt = 0; nt < 4; nt++) {
                    acco[mt][nt][half * 2 + 0] *= s;
                    acco[mt][nt][half * 2 + 1] *= s;
                }
            }
        #pragma unroll
        for (int ks2 = 0; ks2 < 8; ks2++) {
            uint32_t pah[2][4], pal[2][4], vh2[4][2], vl2[4][2];
            int kbt = ks2 * 32 + ((lane >> 4) << 4);   // 0..240
            uint32_t pha = (kbt & 128) ? FA_PHB : FA_PHA;
            uint32_t pla = (kbt & 128) ? FA_PLB : FA_PLA;
            int kbb = kbt & 127;
            #pragma unroll
            for (int mt = 0; mt < 2; mt++) {
                int r = wm * 32 + mt * 16 + (lane & 15);
                uint32_t off = sw128((uint32_t)r, (uint32_t)kbb);
                ldsm4(pah[mt], sbase + pha + off);
                ldsm4(pal[mt], sbase + pla + off);
            }
            int kr = ks2 * 16 + (lane & 15);
            #pragma unroll
            for (int nt = 0; nt < 4; nt++) {
                int nb = (wn * 32 + nt * 8) * 2;
                uint32_t off = sw128((uint32_t)kr, (uint32_t)nb);
                ldsm2t(vh2[nt], sbase + FA_VH + off);
                ldsm2t(vl2[nt], sbase + FA_VL + off);
            }
            #pragma unroll
            for (int mt = 0; mt < 2; mt++)
                #pragma unroll
                for (int nt = 0; nt < 4; nt++) mma_bf16(acco[mt][nt], pah[mt], vh2[nt]);
            #pragma unroll
            for (int mt = 0; mt < 2; mt++)
                #pragma unroll
                for (int nt = 0; nt < 4; nt++) mma_bf16(acco[mt][nt], pah[mt], vl2[nt]);
            #pragma unroll
            for (int mt = 0; mt < 2; mt++)
                #pragma unroll
                for (int nt = 0; nt < 4; nt++) mma_bf16(acco[mt][nt], pal[mt], vh2[nt]);
        }
        __syncthreads();   // all warps done reading V before next V load

        if (kb < 3) {
            load64(sbase + FA_VH, sbase + FA_VL, rowb + (kb + 1) * 128, vcol);
            asm volatile("cp.async.commit_group;" ::: "memory");
        }
    }

    // ---- normalize, split, store ----
    #pragma unroll
    for (int mt = 0; mt < 2; mt++)
        #pragma unroll
        for (int half = 0; half < 2; half++) {
            int r = wm * 32 + mt * 16 + (lane >> 2) + half * 8;
            float inv = 1.0f / l_s[r];
            size_t gp = (rowb + q0 + r) * DDIM + hh * 64;
            #pragma unroll
            for (int nt = 0; nt < 4; nt++) {
                int c = wn * 32 + nt * 8 + (lane & 3) * 2;
                float v0 = acco[mt][nt][half * 2 + 0] * inv;
                float v1 = acco[mt][nt][half * 2 + 1] * inv;
                uint32_t hi, lo;
                split2(v0, v1, hi, lo);
                *(uint32_t*)(Oh + gp + c) = hi;
                *(uint32_t*)(Ol + gp + c) = lo;
            }
        }
}

// ---------------- fp32 -> bf16 hi/lo split (x input only) ----------------
__global__ void split_kernel(const float* __restrict__ in, __nv_bfloat16* __restrict__ hi,
                             __nv_bfloat16* __restrict__ lo, int n4)
{
    int i = blockIdx.x * 256 + threadIdx.x;
    if (i >= n4) return;
    float4 v = ((const float4*)in)[i];
    uint32_t h0, l0, h1, l1;
    split2(v.x, v.y, h0, l0);
    split2(v.z, v.w, h1, l1);
    ((uint2*)hi)[i] = make_uint2(h0, h1);
    ((uint2*)lo)[i] = make_uint2(l0, l1);
}

// ---------------- transposed split ----------------
__global__ void tsplit_kernel(const float* __restrict__ in, __nv_bfloat16* __restrict__ oh,
                              __nv_bfloat16* __restrict__ ol, int K, int N,
                              size_t zin, size_t zout)
{
    __shared__ float tile[32][33];
    const float* inz = in + blockIdx.z * zin;
    __nv_bfloat16* ohz = oh + blockIdx.z * zout;
    __nv_bfloat16* olz = ol + blockIdx.z * zout;
    int tx = threadIdx.x, ty = threadIdx.y;
    int n = blockIdx.x * 32 + tx;
    #pragma unroll
    for (int j = 0; j < 4; j++) {
        int k = blockIdx.y * 32 + ty + j * 8;
        tile[ty + j * 8][tx] = inz[(size_t)k * N + n];
    }
    __syncthreads();
    int ko = blockIdx.y * 32 + tx;
    #pragma unroll
    for (int j = 0; j < 4; j++) {
        int no = blockIdx.x * 32 + ty + j * 8;
        float v = tile[tx][ty + j * 8];
        __nv_bfloat16 h = __float2bfloat16(v);
        __nv_bfloat16 l = __float2bfloat16(v - __bfloat162float(h));
        ohz[(size_t)no * K + ko] = h;
        olz[(size_t)no * K + ko] = l;
    }
}

// ---------------- relative position bias ----------------
__global__ void posbias_kernel(const float* __restrict__ rel_emb, float* __restrict__ pb) {
    int s = blockIdx.x;
    int d = threadIdx.x;
    float acc = 0.f;
    int c0 = s - 31; if (c0 < 0) c0 = 0;
    acc += (float)c0 * rel_emb[0 * DDIM + d];
    int c64 = 480 - s; if (c64 < 0) c64 = 0;
    acc += (float)c64 * rel_emb[64 * DDIM + d];
    #pragma unroll 1
    for (int r = 1; r < 64; r++) {
        int qq = s + r - 32;
        if (qq >= 0 && qq < SDIM) acc += rel_emb[r * DDIM + d];
    }
    pb[s * DDIM + d] = acc * (1.0f / (float)SDIM);
}

// ---------------- block reduce helpers (128 threads) ----------------
__device__ __forceinline__ float blockReduceSum128(float v, float* shm) {
    #pragma unroll
    for (int o = 16; o > 0; o >>= 1) v += __shfl_xor_sync(0xffffffffu, v, o);
    if ((threadIdx.x & 31) == 0) shm[threadIdx.x >> 5] = v;
    __syncthreads();
    v = shm[0] + shm[1] + shm[2] + shm[3];
    __syncthreads();
    return v;
}

// ---------------- layernorm -> fp32 + bf16 hi/lo ----------------
__global__ void layernorm512(const float* __restrict__ in, const float* __restrict__ g,
                             const float* __restrict__ bta, float* __restrict__ out,
                             __nv_bfloat16* __restrict__ oh, __nv_bfloat16* __restrict__ ol)
{
    __shared__ float shm[4];
    size_t row = blockIdx.x;
    const float* p = in + row * DDIM;
    int t = threadIdx.x;
    float4 v = ((const float4*)p)[t];
    float s = v.x + v.y + v.z + v.w;
    s = blockReduceSum128(s, shm);
    float mu = s * (1.0f / (float)DDIM);
    float dx = v.x - mu, dy = v.y - mu, dz = v.z - mu, dw = v.w - mu;
    float sq = dx * dx + dy * dy + dz * dz + dw * dw;
    sq = blockReduceSum128(sq, shm);
    float var = sq * (1.0f / (float)DDIM);
    float inv = rsqrtf(var + 1e-5f);
    float4 gg = ((const float4*)g)[t];
    float4 bb = ((const float4*)bta)[t];
    float4 o;
    o.x = dx * inv * gg.x + bb.x;
    o.y = dy * inv * gg.y + bb.y;
    o.z = dz * inv * gg.z + bb.z;
    o.w = dw * inv * gg.w + bb.w;
    ((float4*)(out + row * DDIM))[t] = o;
    uint32_t h0, l0, h1, l1;
    split2(o.x, o.y, h0, l0);
    split2(o.z, o.w, h1, l1);
    ((uint2*)(oh + row * DDIM))[t] = make_uint2(h0, h1);
    ((uint2*)(ol + row * DDIM))[t] = make_uint2(l0, l1);
}

// ---------------- final projection ----------------
__global__ void outproj(const float* __restrict__ h, const float* __restrict__ W,
                        const float* __restrict__ ob, float* __restrict__ out)
{
    __shared__ float shm[4];
    size_t row = blockIdx.x;
    int t = threadIdx.x;
    float4 v = ((const float4*)(h + row * DDIM))[t];
    float4 w = ((const float4*)W)[t];
    float s = v.x * w.x + v.y * w.y + v.z * w.z + v.w * w.w;
    s = blockReduceSum128(s, shm);
    if (t == 0) out[row] = s + ob[0];
}

extern "C" void kernel_launch(void* const* d_in, const int* in_sizes, int n_in,
                              void* d_out, int out_size)
{
    (void)in_sizes; (void)n_in; (void)out_size;
    const float* x       = (const float*)d_in[0];
    const float* in_W    = (const float*)d_in[1];
    const float* in_b    = (const float*)d_in[2];
    const float* rel_emb = (const float*)d_in[3];
    const float* qkvo_W  = (const float*)d_in[4];
    const float* qkvo_b  = (const float*)d_in[5];
    const float* ln_g    = (const float*)d_in[6];
    const float* ln_b    = (const float*)d_in[7];
    const float* ff_W1   = (const float*)d_in[8];
    const float* ff_b1   = (const float*)d_in[9];
    const float* ff_W2   = (const float*)d_in[10];
    const float* ff_b2   = (const float*)d_in[11];
    const float* out_W   = (const float*)d_in[12];
    const float* out_b   = (const float*)d_in[13];

    float *h, *h1, *tbuf, *pb;
    __nv_bfloat16 *xh, *xl, *ah, *al, *fh, *fl, *qkh, *qkl, *wh, *wl;
    cudaGetSymbolAddress((void**)&h,    g_h);
    cudaGetSymbolAddress((void**)&h1,   g_h1);
    cudaGetSymbolAddress((void**)&tbuf, g_t);
    cudaGetSymbolAddress((void**)&pb,   g_pb);
    cudaGetSymbolAddress((void**)&xh,   g_xh);
    cudaGetSymbolAddress((void**)&xl,   g_xl);
    cudaGetSymbolAddress((void**)&ah,   g_ah);
    cudaGetSymbolAddress((void**)&al,   g_al);
    cudaGetSymbolAddress((void**)&fh,   g_fh);
    cudaGetSymbolAddress((void**)&fl,   g_fl);
    cudaGetSymbolAddress((void**)&qkh,  g_qkh);
    cudaGetSymbolAddress((void**)&qkl,  g_qkl);
    cudaGetSymbolAddress((void**)&wh,   g_wh);
    cudaGetSymbolAddress((void**)&wl,   g_wl);

    auto k_inproj = mma_gemm<false, 2, true,  true,  true >;
    auto k_qkv    = mma_gemm<false, 0, true,  false, true >;
    auto k_res    = mma_gemm<false, 1, true,  true,  false>;
    auto k_ff1    = mma_gemm<true,  0, true,  false, true >;

    cudaFuncSetAttribute(k_inproj, cudaFuncAttributeMaxDynamicSharedMemorySize, DENSE_SMEM);
    cudaFuncSetAttribute(k_qkv,    cudaFuncAttributeMaxDynamicSharedMemorySize, DENSE_SMEM);
    cudaFuncSetAttribute(k_res,    cudaFuncAttributeMaxDynamicSharedMemorySize, DENSE_SMEM);
    cudaFuncSetAttribute(k_ff1,    cudaFuncAttributeMaxDynamicSharedMemorySize, DENSE_SMEM);
    cudaFuncSetAttribute(flash_attn, cudaFuncAttributeMaxDynamicSharedMemorySize, FA_SMEM);

    // ---- weight transpose+split ----
    tsplit_kernel<<<dim3(512 / 32, 64 / 32, 1), dim3(32, 8)>>>(
        in_W, wh + WT_IN, wl + WT_IN, 64, 512, 0, 0);
    tsplit_kernel<<<dim3(16, 16, 24), dim3(32, 8)>>>(
        qkvo_W, wh + WT_QKVO, wl + WT_QKVO, 512, 512,
        (size_t)512 * 512, (size_t)512 * 512);
    tsplit_kernel<<<dim3(2048 / 32, 512 / 32, 6), dim3(32, 8)>>>(
        ff_W1, wh + WT_W1, wl + WT_W1, 512, 2048,
        (size_t)512 * 2048, (size_t)512 * 2048);
    tsplit_kernel<<<dim3(512 / 32, 2048 / 32, 6), dim3(32, 8)>>>(
        ff_W2, wh + WT_W2, wl + WT_W2, 2048, 512,
        (size_t)2048 * 512, (size_t)2048 * 512);

    // ---- position bias & input projection ----
    posbias_kernel<<<SDIM, DDIM>>>(rel_emb, pb);
    split_kernel<<<(MSROWS * 64 / 4 + 255) / 256, 256>>>(x, xh, xl, MSROWS * 64 / 4);
    k_inproj<<<dim3(4, 64), 256, DENSE_SMEM>>>(
        xh, xl, 64, wh + WT_IN, wl + WT_IN, 64, in_b, pb, h, ah, al, DDIM, 64, 1.0f);

    for (int l = 0; l < LNUM; l++) {
        const __nv_bfloat16* Wqkv_h = wh + WT_QKVO + (size_t)l * 4 * 512 * 512;  // q,k,v rows contiguous
        const __nv_bfloat16* Wqkv_l = wl + WT_QKVO + (size_t)l * 4 * 512 * 512;
        const __nv_bfloat16* Wo_h = Wqkv_h + (size_t)3 * 512 * 512;
        const __nv_bfloat16* Wo_l = Wqkv_l + (size_t)3 * 512 * 512;
        const __nv_bfloat16* W1h = wh + WT_W1 + (size_t)l * 2048 * 512;
        const __nv_bfloat16* W1l = wl + WT_W1 + (size_t)l * 2048 * 512;
        const __nv_bfloat16* W2h = wh + WT_W2 + (size_t)l * 512 * 2048;
        const __nv_bfloat16* W2l = wl + WT_W2 + (size_t)l * 512 * 2048;
        const float* bqkv = qkvo_b + (size_t)l * 4 * DDIM;   // q,k,v biases contiguous (1536)
        const float* bo   = bqkv + 3 * DDIM;
        const float* g0   = ln_g + ((size_t)l * 2 + 0) * DDIM;
        const float* b0   = ln_b + ((size_t)l * 2 + 0) * DDIM;
        const float* g1   = ln_g + ((size_t)l * 2 + 1) * DDIM;
        const float* b1l  = ln_b + ((size_t)l * 2 + 1) * DDIM;
        const float* fb1  = ff_b1 + (size_t)l * FDIM;
        const float* fb2  = ff_b2 + (size_t)l * DDIM;

        // fused QKV: (8192 x 1536) = h @ [Wq|Wk|Wv]^T + [bq|bk|bv], split out
        k_qkv<<<dim3(12, 64), 256, DENSE_SMEM>>>(
            ah, al, 512, Wqkv_h, Wqkv_l, 512, bqkv, nullptr,
            nullptr, qkh, qkl, 1536, 512, 1.0f);

        // fused flash attention -> ctx split into ah/al
        flash_attn<<<dim3(BDIM * HDIM, SDIM / 128), 256, FA_SMEM>>>(qkh, qkl, ah, al);

        // o-proj + residual(h) -> tbuf, LN1 -> h1 + ah/al
        k_res<<<dim3(4, 64), 256, DENSE_SMEM>>>(
            ah, al, 512, Wo_h, Wo_l, 512, bo, h, tbuf, nullptr, nullptr, DDIM, 512, 1.0f);
        layernorm512<<<MSROWS, 128>>>(tbuf, g0, b0, h1, ah, al);

        // FF1 (relu) -> fh/fl
        k_ff1<<<dim3(16, 64), 256, DENSE_SMEM>>>(
            ah, al, 512, W1h, W1l, 512, fb1, nullptr, nullptr, fh, fl, FDIM, 512, 1.0f);
        // FF2 + residual(h1) -> tbuf, LN2 -> h + ah/al
        k_res<<<dim3(4, 64), 256, DENSE_SMEM>>>(
            fh, fl, 2048, W2h, W2l, 2048, fb2, h1, tbuf, nullptr, nullptr, DDIM, 2048, 1.0f);
        layernorm512<<<MSROWS, 128>>>(tbuf, g1, b1l, h, ah, al);
    }

    outproj<<<MSROWS, 128>>>(h, out_W, out_b, (float*)d_out);
}